// round 15
// baseline (speedup 1.0000x reference)
#include <cuda_runtime.h>

#define S      1024
#define BATCH  4096
#define HID    4
#define OBSR   8
#define OUTD   8
#define NCHUNK 64           // S / 16

// Scratch: u = relu(BN1(...)) [S,B,4] and h_t [S,B,4] (AoS float4 per element).
__device__ float4 g_U[S * BATCH];   // 64 MB
__device__ float4 g_H[S * BATCH];   // 64 MB

// Producer/consumer sync (monotonic across graph replays; epoch-relative).
__device__ unsigned long long g_epoch;          // ++ per execution (prologue)
__device__ unsigned long long g_cnt1[NCHUNK];   // pass1 CTAs done per 16-t chunk

// Fast activations for the recurrence: single-MUFU tanh.
__device__ __forceinline__ float tanh_a(float x) {
    float y; asm("tanh.approx.f32 %0, %1;" : "=f"(y) : "f"(x)); return y;
}
__device__ __forceinline__ float sig_a(float x) {
    return fmaf(tanh_a(0.5f * x), 0.5f, 0.5f);   // sig(x) = 0.5*tanh(x/2)+0.5
}

// ---------------------------------------------------------------------------
__global__ void prologue_kernel() {
    if (threadIdx.x == 0) g_epoch = g_epoch + 1ULL;
}

// ---------------------------------------------------------------------------
// Pass 1: one CTA (256 thr, 16 elems/thread) per timestep. 256 threads keeps
// regs/CTA ~29K so a pass1 CTA co-resides with a pass2 CTA during overlap.
// After storing U[t], publishes completion to g_cnt1[t/16].
// ---------------------------------------------------------------------------
__global__ void __launch_bounds__(256)
pass1_kernel(const float* __restrict__ obs, const float* __restrict__ ts,
             const float* __restrict__ Wobs, const float* __restrict__ bobs,
             const float* __restrict__ Win,  const float* __restrict__ bin,
             const float* __restrict__ g1,   const float* __restrict__ b1)
{
    __shared__ float sWe[8][4];
    __shared__ float sWt[4][4];
    __shared__ float sbe[4];
    __shared__ float sred[8 * 8];
    __shared__ float sscale[4], sshift[4];

    const int t   = blockIdx.x;
    const int tid = threadIdx.x;   // 256

    if (tid < 32) {
        int k = tid >> 2, j = tid & 3;
        float acc = 0.f;
        #pragma unroll
        for (int m = 0; m < 8; m++) acc += Wobs[k * 8 + m] * Win[m * 4 + j];
        sWe[k][j] = acc;
    } else if (tid < 48) {
        int k = (tid - 32) >> 2, j = tid & 3;
        sWt[k][j] = Win[(8 + k) * 4 + j];
    } else if (tid < 52) {
        int j = tid - 48;
        float acc = bin[j];
        #pragma unroll
        for (int m = 0; m < 8; m++) acc += bobs[m] * Win[m * 4 + j];
        sbe[j] = acc;
    }
    __syncthreads();

    float z[16][4];
    float ps[4] = {0.f, 0.f, 0.f, 0.f};
    float pq[4] = {0.f, 0.f, 0.f, 0.f};

    const float4* obs4 = ((const float4*)obs) + (size_t)t * BATCH * 2;
    const float4* ts4  = ((const float4*)ts)  + (size_t)t * BATCH;

    #pragma unroll
    for (int s = 0; s < 16; s++) {
        int b = tid + s * 256;
        float4 o0 = obs4[b * 2 + 0];
        float4 o1 = obs4[b * 2 + 1];
        float4 tv = ts4[b];
        #pragma unroll
        for (int j = 0; j < 4; j++) {
            float a = sbe[j];
            a += o0.x * sWe[0][j] + o0.y * sWe[1][j] + o0.z * sWe[2][j] + o0.w * sWe[3][j];
            a += o1.x * sWe[4][j] + o1.y * sWe[5][j] + o1.z * sWe[6][j] + o1.w * sWe[7][j];
            a += tv.x * sWt[0][j] + tv.y * sWt[1][j] + tv.z * sWt[2][j] + tv.w * sWt[3][j];
            z[s][j] = a;
            ps[j] += a;
            pq[j] += a * a;
        }
    }

    const int lane = tid & 31, wrp = tid >> 5;   // 8 warps
    #pragma unroll
    for (int j = 0; j < 4; j++) {
        #pragma unroll
        for (int off = 16; off; off >>= 1) {
            ps[j] += __shfl_xor_sync(0xffffffffu, ps[j], off);
            pq[j] += __shfl_xor_sync(0xffffffffu, pq[j], off);
        }
    }
    if (lane == 0) {
        #pragma unroll
        for (int j = 0; j < 4; j++) { sred[wrp * 8 + j] = ps[j]; sred[wrp * 8 + 4 + j] = pq[j]; }
    }
    __syncthreads();
    if (tid < 4) {
        float s0 = 0.f, q0 = 0.f;
        #pragma unroll
        for (int w = 0; w < 8; w++) { s0 += sred[w * 8 + tid]; q0 += sred[w * 8 + 4 + tid]; }
        float m  = s0 * (1.0f / BATCH);
        float v  = q0 * (1.0f / BATCH) - m * m;
        float sc = g1[tid] * rsqrtf(v + 1e-5f);
        sscale[tid] = sc;
        sshift[tid] = b1[tid] - m * sc;
    }
    __syncthreads();

    float4* Up = g_U + (size_t)t * BATCH;
    #pragma unroll
    for (int s = 0; s < 16; s++) {
        int b = tid + s * 256;
        float4 u;
        u.x = fmaxf(z[s][0] * sscale[0] + sshift[0], 0.f);
        u.y = fmaxf(z[s][1] * sscale[1] + sshift[1], 0.f);
        u.z = fmaxf(z[s][2] * sscale[2] + sshift[2], 0.f);
        u.w = fmaxf(z[s][3] * sscale[3] + sshift[3], 0.f);
        Up[b] = u;
    }

    // Release: all threads' stores visible, then one signal per CTA.
    __threadfence();
    __syncthreads();
    if (tid == 0) atomicAdd(&g_cnt1[t >> 4], 1ULL);
}

// ---------------------------------------------------------------------------
// Pass 2: sequential LSTM recurrence (R14-measured design: 4-lane split,
// depth-1 shfls, tanh.approx, one-step-ahead software pipeline, depth-16 ring),
// now gated per 16-t chunk on pass1's flags so it can run CONCURRENTLY with
// pass1. 128 blocks x 128 threads (one warp per SMSP).
// ---------------------------------------------------------------------------
__global__ void __launch_bounds__(128, 1)
pass2_kernel(const float* __restrict__ Wih, const float* __restrict__ Whh,
             const float* __restrict__ bih, const float* __restrict__ bhh)
{
    const int lane = threadIdx.x & 31;
    const int wid  = threadIdx.x >> 5;     // 0..3 -> SMSP
    const int e    = lane >> 2;            // 0..7
    const int k    = lane & 3;             // gate-row slice
    const int b    = blockIdx.x * 32 + wid * 8 + e;

    const unsigned long long tgt = 16ULL * g_epoch;   // per-chunk completion target

#define WAIT_CHUNK(cc)                                                         \
    {                                                                          \
        if (lane == 0) {                                                       \
            while (atomicAdd(&g_cnt1[cc], 0ULL) < tgt) __nanosleep(128);       \
        }                                                                      \
        __syncwarp();                                                          \
        __threadfence();                                                       \
    }

    float wiI[4], wiF[4], wiG[4], wiO[4];
    float whI[4], whF[4], whG[4], whO[4];
    #pragma unroll
    for (int m = 0; m < 4; m++) {
        wiI[m] = Wih[(k     ) * 4 + m];
        wiF[m] = Wih[(4 + k ) * 4 + m];
        wiG[m] = Wih[(8 + k ) * 4 + m];
        wiO[m] = Wih[(12 + k) * 4 + m];
        int km = k ^ m;
        whI[m] = Whh[(k     ) * 4 + km];
        whF[m] = Whh[(4 + k ) * 4 + km];
        whG[m] = Whh[(8 + k ) * 4 + km];
        whO[m] = Whh[(12 + k) * 4 + km];
    }
    const float bI = bih[k]      + bhh[k];
    const float bF = bih[4 + k]  + bhh[4 + k];
    const float bG = bih[8 + k]  + bhh[8 + k];
    const float bO = bih[12 + k] + bhh[12 + k];

    float hk = 0.f, c = 0.f;

    const float4* __restrict__ up = g_U + b;
    float* __restrict__ hp = ((float*)g_H) + (size_t)b * 4 + k;

    WAIT_CHUNK(0)
    float4 ub[16];
    #pragma unroll
    for (int i = 0; i < 16; i++) ub[i] = up[(size_t)i * BATCH];
    up += (size_t)16 * BATCH;

    float aI, aF, aG, aO;
    {
        float4 u = ub[0];
        aI = bI + u.x * wiI[0] + u.y * wiI[1] + u.z * wiI[2] + u.w * wiI[3];
        aF = bF + u.x * wiF[0] + u.y * wiF[1] + u.z * wiF[2] + u.w * wiF[3];
        aG = bG + u.x * wiG[0] + u.y * wiG[1] + u.z * wiG[2] + u.w * wiG[3];
        aO = bO + u.x * wiO[0] + u.y * wiO[1] + u.z * wiO[2] + u.w * wiO[3];
    }

#define P2_STEP(i, PF, LAST)                                                   \
    {                                                                          \
        float ha = __shfl_xor_sync(0xffffffffu, hk, 1);                        \
        float hb = __shfl_xor_sync(0xffffffffu, hk, 2);                        \
        float hc = __shfl_xor_sync(0xffffffffu, hk, 3);                        \
        if (PF) ub[i] = up[(size_t)(i) * BATCH];                               \
        float nI = 0.f, nF = 0.f, nG = 0.f, nO = 0.f;                          \
        if (!LAST) {                                                           \
            float4 un = ub[((i) + 1) & 15];                                    \
            nI = bI + un.x * wiI[0] + un.y * wiI[1] + un.z * wiI[2] + un.w * wiI[3]; \
            nF = bF + un.x * wiF[0] + un.y * wiF[1] + un.z * wiF[2] + un.w * wiF[3]; \
            nG = bG + un.x * wiG[0] + un.y * wiG[1] + un.z * wiG[2] + un.w * wiG[3]; \
            nO = bO + un.x * wiO[0] + un.y * wiO[1] + un.z * wiO[2] + un.w * wiO[3]; \
        }                                                                      \
        float gI = aI + ((hk * whI[0] + ha * whI[1]) + (hb * whI[2] + hc * whI[3])); \
        float gF = aF + ((hk * whF[0] + ha * whF[1]) + (hb * whF[2] + hc * whF[3])); \
        float gG = aG + ((hk * whG[0] + ha * whG[1]) + (hb * whG[2] + hc * whG[3])); \
        float gO = aO + ((hk * whO[0] + ha * whO[1]) + (hb * whO[2] + hc * whO[3])); \
        c  = sig_a(gF) * c + sig_a(gI) * tanh_a(gG);                           \
        hk = sig_a(gO) * tanh_a(c);                                            \
        hp[0] = hk;                                                            \
        hp += (size_t)BATCH * 4;                                               \
        aI = nI; aF = nF; aG = nG; aO = nO;                                    \
    }

    int ck = 1;
    for (int t = 0; t < S - 16; t += 16, ck++) {
        WAIT_CHUNK(ck)             // gate the prefetches into chunk ck
        #pragma unroll
        for (int i = 0; i < 16; i++) P2_STEP(i, true, false)
        up += (size_t)16 * BATCH;
    }
    #pragma unroll
    for (int i = 0; i < 16; i++) P2_STEP(i, false, (i == 15))
#undef P2_STEP
#undef WAIT_CHUNK
}

// ---------------------------------------------------------------------------
// Pass 3: one CTA (1024 thr) per timestep; 4 elements/thread cached in regs.
// BN2 stats over batch, y = BN2(h)@W_out + b_out, stats folded into [4x8]+[8].
// ---------------------------------------------------------------------------
__global__ void __launch_bounds__(1024, 1)
pass3_kernel(float* __restrict__ out,
             const float* __restrict__ g2,   const float* __restrict__ b2,
             const float* __restrict__ Wout, const float* __restrict__ bout)
{
    __shared__ float sred[32 * 8];
    __shared__ float sscale[4], sshift[4];
    __shared__ float sW[4][8];
    __shared__ float sB[8];

    const int t   = blockIdx.x;
    const int tid = threadIdx.x;   // 1024

    const float4* Hp = g_H + (size_t)t * BATCH;

    float4 hv[4];
    float ps[4] = {0.f, 0.f, 0.f, 0.f};
    float pq[4] = {0.f, 0.f, 0.f, 0.f};
    #pragma unroll
    for (int s = 0; s < 4; s++) {
        int b = tid + s * 1024;
        float4 v = Hp[b];
        hv[s] = v;
        ps[0] += v.x; pq[0] += v.x * v.x;
        ps[1] += v.y; pq[1] += v.y * v.y;
        ps[2] += v.z; pq[2] += v.z * v.z;
        ps[3] += v.w; pq[3] += v.w * v.w;
    }

    const int lane = tid & 31, wrp = tid >> 5;
    #pragma unroll
    for (int j = 0; j < 4; j++) {
        #pragma unroll
        for (int off = 16; off; off >>= 1) {
            ps[j] += __shfl_xor_sync(0xffffffffu, ps[j], off);
            pq[j] += __shfl_xor_sync(0xffffffffu, pq[j], off);
        }
    }
    if (lane == 0) {
        #pragma unroll
        for (int j = 0; j < 4; j++) { sred[wrp * 8 + j] = ps[j]; sred[wrp * 8 + 4 + j] = pq[j]; }
    }
    __syncthreads();
    if (tid < 4) {
        float s0 = 0.f, q0 = 0.f;
        #pragma unroll
        for (int w = 0; w < 32; w++) { s0 += sred[w * 8 + tid]; q0 += sred[w * 8 + 4 + tid]; }
        float m  = s0 * (1.0f / BATCH);
        float v  = q0 * (1.0f / BATCH) - m * m;
        float sc = g2[tid] * rsqrtf(v + 1e-5f);
        sscale[tid] = sc;
        sshift[tid] = b2[tid] - m * sc;
    }
    __syncthreads();
    if (tid < 32) {
        int kk = tid >> 3, j = tid & 7;
        sW[kk][j] = sscale[kk] * Wout[kk * 8 + j];
    } else if (tid < 40) {
        int j = tid - 32;
        float acc = bout[j];
        #pragma unroll
        for (int kk = 0; kk < 4; kk++) acc += sshift[kk] * Wout[kk * 8 + j];
        sB[j] = acc;
    }
    __syncthreads();

    float4* out4 = ((float4*)out) + (size_t)t * BATCH * 2;
    #pragma unroll
    for (int s = 0; s < 4; s++) {
        int b = tid + s * 1024;
        float4 v = hv[s];
        float y[8];
        #pragma unroll
        for (int j = 0; j < 8; j++) {
            y[j] = sB[j] + v.x * sW[0][j] + v.y * sW[1][j] + v.z * sW[2][j] + v.w * sW[3][j];
        }
        out4[b * 2 + 0] = make_float4(y[0], y[1], y[2], y[3]);
        out4[b * 2 + 1] = make_float4(y[4], y[5], y[6], y[7]);
    }
}

// ---------------------------------------------------------------------------
// Launch graph:  s0: prologue -> [e1] -> pass1
//                s2: wait(e1) -> pass2 (flag-gated vs pass1) -> pass3 -> [e2]
//                s0: wait(e2)
// Streams/events created per call (called <=3 times; leaked, no device memory).
// ---------------------------------------------------------------------------
extern "C" void kernel_launch(void* const* d_in, const int* in_sizes, int n_in,
                              void* d_out, int out_size)
{
    const float* obs  = (const float*)d_in[0];
    const float* ts   = (const float*)d_in[1];
    const float* Wobs = (const float*)d_in[2];
    const float* bobs = (const float*)d_in[3];
    const float* Win  = (const float*)d_in[4];
    const float* bin  = (const float*)d_in[5];
    const float* g1   = (const float*)d_in[6];
    const float* b1   = (const float*)d_in[7];
    const float* Wih  = (const float*)d_in[8];
    const float* Whh  = (const float*)d_in[9];
    const float* bih  = (const float*)d_in[10];
    const float* bhh  = (const float*)d_in[11];
    const float* g2   = (const float*)d_in[12];
    const float* b2   = (const float*)d_in[13];
    const float* Wout = (const float*)d_in[14];
    const float* bout = (const float*)d_in[15];

    cudaStream_t s2;
    cudaEvent_t  e1, e2;
    cudaStreamCreateWithFlags(&s2, cudaStreamNonBlocking);
    cudaEventCreateWithFlags(&e1, cudaEventDisableTiming);
    cudaEventCreateWithFlags(&e2, cudaEventDisableTiming);

    prologue_kernel<<<1, 1>>>();
    cudaEventRecord(e1, 0);
    pass1_kernel<<<S, 256>>>(obs, ts, Wobs, bobs, Win, bin, g1, b1);

    cudaStreamWaitEvent(s2, e1, 0);
    pass2_kernel<<<BATCH / 32, 128, 0, s2>>>(Wih, Whh, bih, bhh);
    pass3_kernel<<<S, 1024, 0, s2>>>((float*)d_out, g2, b2, Wout, bout);
    cudaEventRecord(e2, s2);

    cudaStreamWaitEvent(0, e2, 0);
}

// round 16
// speedup vs baseline: 1.3811x; 1.3811x over previous
#include <cuda_runtime.h>

#define S      1024
#define BATCH  4096
#define HID    4
#define OBSR   8
#define OUTD   8

// Scratch: u = relu(BN1(...)) [S,B,4] and h_t [S,B,4] (AoS float4 per element).
__device__ float4 g_U[S * BATCH];   // 64 MB
__device__ float4 g_H[S * BATCH];   // 64 MB
__device__ float  g_stats[S][8];    // per-t BN2 folded scale[4], shift[4]

// Fast activations for the recurrence: single-MUFU tanh.
__device__ __forceinline__ float tanh_a(float x) {
    float y; asm("tanh.approx.f32 %0, %1;" : "=f"(y) : "f"(x)); return y;
}
__device__ __forceinline__ float sig_a(float x) {
    return fmaf(tanh_a(0.5f * x), 0.5f, 0.5f);   // sig(x) = 0.5*tanh(x/2)+0.5
}

// ---------------------------------------------------------------------------
// Pass 1 (R14-measured, 68.4us): one CTA (512 thr) per timestep,
// 8 elements/thread cached in regs. z = obs@W_eff + ts@W_ts + b_eff; BN1; relu.
// ---------------------------------------------------------------------------
__global__ void __launch_bounds__(512)
pass1_kernel(const float* __restrict__ obs, const float* __restrict__ ts,
             const float* __restrict__ Wobs, const float* __restrict__ bobs,
             const float* __restrict__ Win,  const float* __restrict__ bin,
             const float* __restrict__ g1,   const float* __restrict__ b1)
{
    __shared__ float sWe[8][4];
    __shared__ float sWt[4][4];
    __shared__ float sbe[4];
    __shared__ float sred[16 * 8];
    __shared__ float sscale[4], sshift[4];

    const int t   = blockIdx.x;
    const int tid = threadIdx.x;   // 512

    if (tid < 32) {
        int k = tid >> 2, j = tid & 3;
        float acc = 0.f;
        #pragma unroll
        for (int m = 0; m < 8; m++) acc += Wobs[k * 8 + m] * Win[m * 4 + j];
        sWe[k][j] = acc;
    } else if (tid < 48) {
        int k = (tid - 32) >> 2, j = tid & 3;
        sWt[k][j] = Win[(8 + k) * 4 + j];
    } else if (tid < 52) {
        int j = tid - 48;
        float acc = bin[j];
        #pragma unroll
        for (int m = 0; m < 8; m++) acc += bobs[m] * Win[m * 4 + j];
        sbe[j] = acc;
    }
    __syncthreads();

    float z[8][4];
    float ps[4] = {0.f, 0.f, 0.f, 0.f};
    float pq[4] = {0.f, 0.f, 0.f, 0.f};

    const float4* obs4 = ((const float4*)obs) + (size_t)t * BATCH * 2;
    const float4* ts4  = ((const float4*)ts)  + (size_t)t * BATCH;

    #pragma unroll
    for (int s = 0; s < 8; s++) {
        int b = tid + s * 512;
        float4 o0 = obs4[b * 2 + 0];
        float4 o1 = obs4[b * 2 + 1];
        float4 tv = ts4[b];
        #pragma unroll
        for (int j = 0; j < 4; j++) {
            float a = sbe[j];
            a += o0.x * sWe[0][j] + o0.y * sWe[1][j] + o0.z * sWe[2][j] + o0.w * sWe[3][j];
            a += o1.x * sWe[4][j] + o1.y * sWe[5][j] + o1.z * sWe[6][j] + o1.w * sWe[7][j];
            a += tv.x * sWt[0][j] + tv.y * sWt[1][j] + tv.z * sWt[2][j] + tv.w * sWt[3][j];
            z[s][j] = a;
            ps[j] += a;
            pq[j] += a * a;
        }
    }

    const int lane = tid & 31, wrp = tid >> 5;
    #pragma unroll
    for (int j = 0; j < 4; j++) {
        #pragma unroll
        for (int off = 16; off; off >>= 1) {
            ps[j] += __shfl_xor_sync(0xffffffffu, ps[j], off);
            pq[j] += __shfl_xor_sync(0xffffffffu, pq[j], off);
        }
    }
    if (lane == 0) {
        #pragma unroll
        for (int j = 0; j < 4; j++) { sred[wrp * 8 + j] = ps[j]; sred[wrp * 8 + 4 + j] = pq[j]; }
    }
    __syncthreads();
    if (tid < 4) {
        float s0 = 0.f, q0 = 0.f;
        #pragma unroll
        for (int w = 0; w < 16; w++) { s0 += sred[w * 8 + tid]; q0 += sred[w * 8 + 4 + tid]; }
        float m  = s0 * (1.0f / BATCH);
        float v  = q0 * (1.0f / BATCH) - m * m;
        float sc = g1[tid] * rsqrtf(v + 1e-5f);
        sscale[tid] = sc;
        sshift[tid] = b1[tid] - m * sc;
    }
    __syncthreads();

    float4* Up = g_U + (size_t)t * BATCH;
    #pragma unroll
    for (int s = 0; s < 8; s++) {
        int b = tid + s * 512;
        float4 u;
        u.x = fmaxf(z[s][0] * sscale[0] + sshift[0], 0.f);
        u.y = fmaxf(z[s][1] * sscale[1] + sshift[1], 0.f);
        u.z = fmaxf(z[s][2] * sscale[2] + sshift[2], 0.f);
        u.w = fmaxf(z[s][3] * sscale[3] + sshift[3], 0.f);
        Up[b] = u;
    }
}

// ---------------------------------------------------------------------------
// Pass 2 (R14-measured, ~125us): single chain/thread, 4-lane split, depth-1
// shfls, tanh.approx, one-step-ahead software pipeline, depth-16 ring.
// 128 blocks x 128 threads (one warp per SMSP). NOTHING co-schedules with it.
// ---------------------------------------------------------------------------
__global__ void __launch_bounds__(128, 1)
pass2_kernel(const float* __restrict__ Wih, const float* __restrict__ Whh,
             const float* __restrict__ bih, const float* __restrict__ bhh)
{
    const int lane = threadIdx.x & 31;
    const int wid  = threadIdx.x >> 5;     // 0..3 -> SMSP
    const int e    = lane >> 2;            // 0..7
    const int k    = lane & 3;             // gate-row slice
    const int b    = blockIdx.x * 32 + wid * 8 + e;

    float wiI[4], wiF[4], wiG[4], wiO[4];
    float whI[4], whF[4], whG[4], whO[4];
    #pragma unroll
    for (int m = 0; m < 4; m++) {
        wiI[m] = Wih[(k     ) * 4 + m];
        wiF[m] = Wih[(4 + k ) * 4 + m];
        wiG[m] = Wih[(8 + k ) * 4 + m];
        wiO[m] = Wih[(12 + k) * 4 + m];
        int km = k ^ m;
        whI[m] = Whh[(k     ) * 4 + km];
        whF[m] = Whh[(4 + k ) * 4 + km];
        whG[m] = Whh[(8 + k ) * 4 + km];
        whO[m] = Whh[(12 + k) * 4 + km];
    }
    const float bI = bih[k]      + bhh[k];
    const float bF = bih[4 + k]  + bhh[4 + k];
    const float bG = bih[8 + k]  + bhh[8 + k];
    const float bO = bih[12 + k] + bhh[12 + k];

    float hk = 0.f, c = 0.f;

    const float4* __restrict__ up = g_U + b;
    float* __restrict__ hp = ((float*)g_H) + (size_t)b * 4 + k;

    float4 ub[16];
    #pragma unroll
    for (int i = 0; i < 16; i++) ub[i] = up[(size_t)i * BATCH];
    up += (size_t)16 * BATCH;

    float aI, aF, aG, aO;
    {
        float4 u = ub[0];
        aI = bI + u.x * wiI[0] + u.y * wiI[1] + u.z * wiI[2] + u.w * wiI[3];
        aF = bF + u.x * wiF[0] + u.y * wiF[1] + u.z * wiF[2] + u.w * wiF[3];
        aG = bG + u.x * wiG[0] + u.y * wiG[1] + u.z * wiG[2] + u.w * wiG[3];
        aO = bO + u.x * wiO[0] + u.y * wiO[1] + u.z * wiO[2] + u.w * wiO[3];
    }

#define P2_STEP(i, PF, LAST)                                                   \
    {                                                                          \
        float ha = __shfl_xor_sync(0xffffffffu, hk, 1);                        \
        float hb = __shfl_xor_sync(0xffffffffu, hk, 2);                        \
        float hc = __shfl_xor_sync(0xffffffffu, hk, 3);                        \
        if (PF) ub[i] = up[(size_t)(i) * BATCH];                               \
        float nI = 0.f, nF = 0.f, nG = 0.f, nO = 0.f;                          \
        if (!LAST) {                                                           \
            float4 un = ub[((i) + 1) & 15];                                    \
            nI = bI + un.x * wiI[0] + un.y * wiI[1] + un.z * wiI[2] + un.w * wiI[3]; \
            nF = bF + un.x * wiF[0] + un.y * wiF[1] + un.z * wiF[2] + un.w * wiF[3]; \
            nG = bG + un.x * wiG[0] + un.y * wiG[1] + un.z * wiG[2] + un.w * wiG[3]; \
            nO = bO + un.x * wiO[0] + un.y * wiO[1] + un.z * wiO[2] + un.w * wiO[3]; \
        }                                                                      \
        float gI = aI + ((hk * whI[0] + ha * whI[1]) + (hb * whI[2] + hc * whI[3])); \
        float gF = aF + ((hk * whF[0] + ha * whF[1]) + (hb * whF[2] + hc * whF[3])); \
        float gG = aG + ((hk * whG[0] + ha * whG[1]) + (hb * whG[2] + hc * whG[3])); \
        float gO = aO + ((hk * whO[0] + ha * whO[1]) + (hb * whO[2] + hc * whO[3])); \
        c  = sig_a(gF) * c + sig_a(gI) * tanh_a(gG);                           \
        hk = sig_a(gO) * tanh_a(c);                                            \
        hp[0] = hk;                                                            \
        hp += (size_t)BATCH * 4;                                               \
        aI = nI; aF = nF; aG = nG; aO = nO;                                    \
    }

    for (int t = 0; t < S - 16; t += 16) {
        #pragma unroll
        for (int i = 0; i < 16; i++) P2_STEP(i, true, false)
        up += (size_t)16 * BATCH;
    }
    #pragma unroll
    for (int i = 0; i < 16; i++) P2_STEP(i, false, (i == 15))
#undef P2_STEP
}

// ---------------------------------------------------------------------------
// Pass 3a: BN2 stats only. One CTA (512 thr, 8 elem) per timestep; pure read
// stream + reduction, low regs -> multiple CTAs/SM. Writes folded scale/shift.
// ---------------------------------------------------------------------------
__global__ void __launch_bounds__(512)
pass3_stats_kernel(const float* __restrict__ g2, const float* __restrict__ b2)
{
    __shared__ float sred[16 * 8];

    const int t   = blockIdx.x;
    const int tid = threadIdx.x;   // 512

    const float4* Hp = g_H + (size_t)t * BATCH;

    float ps[4] = {0.f, 0.f, 0.f, 0.f};
    float pq[4] = {0.f, 0.f, 0.f, 0.f};
    #pragma unroll
    for (int s = 0; s < 8; s++) {
        float4 v = Hp[tid + s * 512];
        ps[0] += v.x; pq[0] += v.x * v.x;
        ps[1] += v.y; pq[1] += v.y * v.y;
        ps[2] += v.z; pq[2] += v.z * v.z;
        ps[3] += v.w; pq[3] += v.w * v.w;
    }

    const int lane = tid & 31, wrp = tid >> 5;
    #pragma unroll
    for (int j = 0; j < 4; j++) {
        #pragma unroll
        for (int off = 16; off; off >>= 1) {
            ps[j] += __shfl_xor_sync(0xffffffffu, ps[j], off);
            pq[j] += __shfl_xor_sync(0xffffffffu, pq[j], off);
        }
    }
    if (lane == 0) {
        #pragma unroll
        for (int j = 0; j < 4; j++) { sred[wrp * 8 + j] = ps[j]; sred[wrp * 8 + 4 + j] = pq[j]; }
    }
    __syncthreads();
    if (tid < 4) {
        float s0 = 0.f, q0 = 0.f;
        #pragma unroll
        for (int w = 0; w < 16; w++) { s0 += sred[w * 8 + tid]; q0 += sred[w * 8 + 4 + tid]; }
        float m  = s0 * (1.0f / BATCH);
        float v  = q0 * (1.0f / BATCH) - m * m;
        float sc = g2[tid] * rsqrtf(v + 1e-5f);
        g_stats[t][tid]     = sc;
        g_stats[t][4 + tid] = b2[tid] - m * sc;
    }
}

// ---------------------------------------------------------------------------
// Pass 3b: apply. One CTA (512 thr, 8 elem) per timestep; loads 8 consts to
// smem (one tiny barrier), then pure load->FMA->store stream, low regs.
// ---------------------------------------------------------------------------
__global__ void __launch_bounds__(512)
pass3_apply_kernel(float* __restrict__ out,
                   const float* __restrict__ Wout, const float* __restrict__ bout)
{
    __shared__ float sW[4][8];
    __shared__ float sB[8];

    const int t   = blockIdx.x;
    const int tid = threadIdx.x;   // 512

    if (tid < 32) {
        int kk = tid >> 3, j = tid & 7;
        sW[kk][j] = g_stats[t][kk] * Wout[kk * 8 + j];
    } else if (tid < 40) {
        int j = tid - 32;
        float acc = bout[j];
        #pragma unroll
        for (int kk = 0; kk < 4; kk++) acc += g_stats[t][4 + kk] * Wout[kk * 8 + j];
        sB[j] = acc;
    }
    __syncthreads();

    const float4* Hp = g_H + (size_t)t * BATCH;
    float4* out4 = ((float4*)out) + (size_t)t * BATCH * 2;

    #pragma unroll
    for (int s = 0; s < 8; s++) {
        int b = tid + s * 512;
        float4 v = Hp[b];
        float y[8];
        #pragma unroll
        for (int j = 0; j < 8; j++) {
            y[j] = sB[j] + v.x * sW[0][j] + v.y * sW[1][j] + v.z * sW[2][j] + v.w * sW[3][j];
        }
        out4[b * 2 + 0] = make_float4(y[0], y[1], y[2], y[3]);
        out4[b * 2 + 1] = make_float4(y[4], y[5], y[6], y[7]);
    }
}

// ---------------------------------------------------------------------------
extern "C" void kernel_launch(void* const* d_in, const int* in_sizes, int n_in,
                              void* d_out, int out_size)
{
    const float* obs  = (const float*)d_in[0];
    const float* ts   = (const float*)d_in[1];
    const float* Wobs = (const float*)d_in[2];
    const float* bobs = (const float*)d_in[3];
    const float* Win  = (const float*)d_in[4];
    const float* bin  = (const float*)d_in[5];
    const float* g1   = (const float*)d_in[6];
    const float* b1   = (const float*)d_in[7];
    const float* Wih  = (const float*)d_in[8];
    const float* Whh  = (const float*)d_in[9];
    const float* bih  = (const float*)d_in[10];
    const float* bhh  = (const float*)d_in[11];
    const float* g2   = (const float*)d_in[12];
    const float* b2   = (const float*)d_in[13];
    const float* Wout = (const float*)d_in[14];
    const float* bout = (const float*)d_in[15];

    pass1_kernel<<<S, 512>>>(obs, ts, Wobs, bobs, Win, bin, g1, b1);
    pass2_kernel<<<BATCH / 32, 128>>>(Wih, Whh, bih, bhh);
    pass3_stats_kernel<<<S, 512>>>(g2, b2);
    pass3_apply_kernel<<<S, 512>>>((float*)d_out, Wout, bout);
}